// round 8
// baseline (speedup 1.0000x reference)
#include <cuda_runtime.h>
#include <cuda_fp16.h>
#include <cstdint>

#define NB 4
#define NS 4096
#define ND 64
#define SCALE 0.125f
#define STR 72u          // fp16 elems per smem row (144 B -> LDSM conflict-free)
#define TBYTES 9216u     // one 64x72 fp16 tile
#define BUFB 27648u      // one buffer group: KH + KL + VH

// dynamic smem: [Q 9216][3 x (KH 9216, KL 9216, VH 9216)]
#define O_Q 0u
#define O_B 9216u
#define SMEM_SZ 92160u

// pre-split fp16 operand arrays (uint32 = fp16x2), rows of 128 B
__device__ __align__(128) uint32_t g_qh[(size_t)NB * NS * 32];  // fp16(q*SCALE)
__device__ __align__(128) uint32_t g_kh[(size_t)NB * NS * 32];  // fp16 hi of kn
__device__ __align__(128) uint32_t g_kl[(size_t)NB * NS * 32];  // fp16 lo of kn
__device__ __align__(128) uint32_t g_vh[(size_t)NB * NS * 32];  // fp16(v)
__device__ float g_shift[NB * NS];

// ------------------------------------------------------------- PTX helpers
__device__ __forceinline__ uint32_t smem_u32(const void* p) {
    uint32_t a;
    asm("{ .reg .u64 t; cvta.to.shared.u64 t, %1; cvt.u32.u64 %0, t; }" : "=r"(a) : "l"(p));
    return a;
}
__device__ __forceinline__ uint64_t gaddr(const void* p) {
    uint64_t a;
    asm("cvta.to.global.u64 %0, %1;" : "=l"(a) : "l"(p));
    return a;
}
__device__ __forceinline__ void cp16(uint32_t dst, uint64_t src) {
    asm volatile("cp.async.cg.shared.global [%0], [%1], 16;" ::"r"(dst), "l"(src));
}
#define CP_COMMIT() asm volatile("cp.async.commit_group;" ::: "memory")
#define CP_WAIT0()  asm volatile("cp.async.wait_group 0;" ::: "memory")
#define CP_WAIT1()  asm volatile("cp.async.wait_group 1;" ::: "memory")

__device__ __forceinline__ void ldsm4(uint32_t* d, uint32_t a) {
    asm volatile("ldmatrix.sync.aligned.m8n8.x4.shared.b16 {%0,%1,%2,%3}, [%4];"
                 : "=r"(d[0]), "=r"(d[1]), "=r"(d[2]), "=r"(d[3]) : "r"(a));
}
__device__ __forceinline__ void ldsm4t(uint32_t* d, uint32_t a) {
    asm volatile("ldmatrix.sync.aligned.m8n8.x4.trans.shared.b16 {%0,%1,%2,%3}, [%4];"
                 : "=r"(d[0]), "=r"(d[1]), "=r"(d[2]), "=r"(d[3]) : "r"(a));
}
__device__ __forceinline__ void mma_f16(float* c, const uint32_t* a, uint32_t b0, uint32_t b1) {
    asm volatile("mma.sync.aligned.m16n8k16.row.col.f32.f16.f16.f32 "
                 "{%0,%1,%2,%3}, {%4,%5,%6,%7}, {%8,%9}, {%0,%1,%2,%3};"
                 : "+f"(c[0]), "+f"(c[1]), "+f"(c[2]), "+f"(c[3])
                 : "r"(a[0]), "r"(a[1]), "r"(a[2]), "r"(a[3]), "r"(b0), "r"(b1));
}
__device__ __forceinline__ uint32_t h2u(__half2 h) { return *reinterpret_cast<uint32_t*>(&h); }
__device__ __forceinline__ void splith(float a, float b, uint32_t& hi, uint32_t& lo) {
    __half2 h = __floats2half2_rn(a, b);
    float2 f = __half22float2(h);
    __half2 l = __floats2half2_rn(a - f.x, b - f.y);
    hi = h2u(h);
    lo = h2u(l);
}

// ---------------------------------------------------------------------------
// Kernel 1: norms -> shift; fp16 Q*SCALE, split Kn (hi/lo), fp16 V.
// ---------------------------------------------------------------------------
__global__ void prep_kernel(const float* __restrict__ qk, const float* __restrict__ v) {
    int row = blockIdx.x * 8 + (threadIdx.x >> 5);
    int lane = threadIdx.x & 31;
    float2 q = *(const float2*)(qk + (size_t)row * ND + lane * 2);
    float ss = q.x * q.x + q.y * q.y;
    #pragma unroll
    for (int o = 16; o >= 1; o >>= 1) ss += __shfl_xor_sync(0xffffffffu, ss, o);
    float nrm = fmaxf(sqrtf(ss), 1e-12f);
    float inv = 1.0f / nrm;
    size_t w = (size_t)row * 32 + lane;
    g_qh[w] = h2u(__floats2half2_rn(q.x * SCALE, q.y * SCALE));
    uint32_t hi, lo;
    splith(q.x * inv, q.y * inv, hi, lo);
    g_kh[w] = hi; g_kl[w] = lo;
    float2 vv = *(const float2*)(v + (size_t)row * ND + lane * 2);
    g_vh[w] = h2u(__floats2half2_rn(vv.x, vv.y));
    if (lane == 0) g_shift[row] = nrm * SCALE;
}

// ---------------------------------------------------------------------------
// Kernel 2: fully fused: QK^T (2-term) -> exp -> unnormalized attn -> P@V
// -> in-CTA normalize sweep + upper-tri zero-fill. 3-stage cp.async pipeline.
// ---------------------------------------------------------------------------
__global__ __launch_bounds__(128)
void attn_main(const float* __restrict__ v,
               float* __restrict__ out, float* __restrict__ attn)
{
    extern __shared__ char smc[];
    const uint32_t sb = smem_u32(smc);
    const int tid = threadIdx.x, lane = tid & 31, w = tid >> 5;

    // balanced schedule: paired SMs sum to 65 tile-iters
    int l = blockIdx.x, rt, b;
    if (l < 40)       { rt = 63 - (l >> 2); b = l & 3; }
    else if (l < 148) { int i = l - 40; rt = 53 - (i >> 2); b = i & 3; }
    else              { int i = l - 148; rt = i >> 2; b = i & 3; }
    const size_t bS = (size_t)b * NS;
    const int nt = rt + 1;

    __shared__ float shift_s[64];
    __shared__ float rowsum_s[64];
    if (tid < 64) shift_s[tid] = g_shift[bS + rt * 64 + tid];

    const uint64_t gqh = gaddr(g_qh);
    const uint64_t gkh = gaddr(g_kh), gkl = gaddr(g_kl);
    const uint64_t gvh = gaddr(g_vh);

    auto issue_kv = [&](int ct, uint32_t buf) {
        size_t t0 = (bS + (size_t)ct * 64) * 128;
        uint32_t kb = sb + O_B + buf * BUFB;
        #pragma unroll
        for (int c = 0; c < 4; ++c) {
            int idx = tid * 4 + c, r = idx >> 3, c8 = idx & 7;
            uint32_t so = (uint32_t)(r * 144 + c8 * 16);
            uint64_t go = t0 + (size_t)r * 128 + c8 * 16;
            cp16(kb + so, gkh + go);
            cp16(kb + TBYTES + so, gkl + go);
            cp16(kb + 2 * TBYTES + so, gvh + go);
        }
    };
    // prologue: group0 = Q + tile0; group1 = tile1 (if any)
    {
        size_t q0 = (bS + (size_t)rt * 64) * 128;
        #pragma unroll
        for (int c = 0; c < 4; ++c) {
            int idx = tid * 4 + c, r = idx >> 3, c8 = idx & 7;
            cp16(sb + O_Q + (uint32_t)(r * 144 + c8 * 16),
                 gqh + q0 + (size_t)r * 128 + c8 * 16);
        }
        issue_kv(0, 0);
        CP_COMMIT();
        if (nt > 1) issue_kv(1, 1);
        CP_COMMIT();
    }

    // ldmatrix byte-offset helpers (within a tile)
    const uint32_t A_off  = (uint32_t)(((lane & 15) * STR + ((lane >> 4) << 3)) * 2);
    const uint32_t B_off  = (uint32_t)(((((lane >> 4) << 3) + (lane & 7)) * STR + (((lane >> 3) & 1) << 3)) * 2);
    const uint32_t Vt_off = (uint32_t)(((lane & 15) * STR + ((lane >> 4) << 3)) * 2);

    const int g = lane >> 2, t = lane & 3;
    const int r0 = w * 16 + g;
    const int gi0 = rt * 64 + r0, gi1 = gi0 + 8;
    const float sh0 = shift_s[r0], sh1 = shift_s[r0 + 8];
    float* attn_b = attn + (size_t)b * NS * NS;
    float* arow0 = attn_b + (size_t)gi0 * NS;
    float* arow1 = attn_b + (size_t)gi1 * NS;

    float oc[8][4] = {};
    float rs0 = 0.f, rs1 = 0.f;

    for (int ct = 0; ct < nt; ++ct) {
        const uint32_t buf = (uint32_t)(ct % 3);
        if (ct == 0) CP_WAIT0(); else CP_WAIT1();
        __syncthreads();
        if (ct + 2 < nt) issue_kv(ct + 2, (uint32_t)((ct + 2) % 3));
        CP_COMMIT();

        // --- preload all V fragments for this tile (kills AV LDSM stalls) ---
        uint32_t vfr[4][4][4];
        const uint32_t vhb = sb + O_B + buf * BUFB + 2 * TBYTES;
        #pragma unroll
        for (int kb = 0; kb < 4; ++kb)
            #pragma unroll
            for (int ep = 0; ep < 4; ++ep)
                ldsm4t(vfr[kb][ep], vhb + Vt_off + (uint32_t)(kb * 16 * STR * 2) + (uint32_t)(ep * 32));

        // --- S = Qs @ Kn^T (2-term: aq*kh + aq*kl) ---
        float sc[8][4] = {};
        const uint32_t khb = sb + O_B + buf * BUFB, klb = khb + TBYTES;
        #pragma unroll
        for (int k = 0; k < 4; ++k) {
            uint32_t aq[4], bh[4], bl[4];
            uint32_t kcol = (uint32_t)(k * 16 * 2);
            ldsm4(aq, sb + O_Q + A_off + kcol + (uint32_t)(w * 16 * STR * 2));
            #pragma unroll
            for (int np = 0; np < 4; ++np) {
                uint32_t jo = (uint32_t)(np * 16 * STR * 2);
                ldsm4(bh, khb + B_off + jo + kcol);
                ldsm4(bl, klb + B_off + jo + kcol);
                mma_f16(sc[2 * np],     aq, bh[0], bh[1]);
                mma_f16(sc[2 * np],     aq, bl[0], bl[1]);
                mma_f16(sc[2 * np + 1], aq, bh[2], bh[3]);
                mma_f16(sc[2 * np + 1], aq, bl[2], bl[3]);
            }
        }

        // --- exp + mask + unnormalized attn store + fp16 A-frag repack ---
        uint32_t ah_[4][4];
        const int gjb = ct * 64 + 2 * t;
        #pragma unroll
        for (int nb = 0; nb < 8; ++nb) {
            int gj = gjb + nb * 8;
            float p00 = (gj < gi0)     ? __expf(sc[nb][0] - sh0) : 0.f;
            float p01 = (gj + 1 < gi0) ? __expf(sc[nb][1] - sh0) : 0.f;
            float p10 = (gj < gi1)     ? __expf(sc[nb][2] - sh1) : 0.f;
            float p11 = (gj + 1 < gi1) ? __expf(sc[nb][3] - sh1) : 0.f;
            rs0 += p00 + p01;
            rs1 += p10 + p11;
            *(float2*)(arow0 + gj) = make_float2(p00, p01);
            *(float2*)(arow1 + gj) = make_float2(p10, p11);
            int kb = nb >> 1, o = (nb & 1) * 2;
            ah_[kb][o]     = h2u(__floats2half2_rn(p00, p01));
            ah_[kb][o + 1] = h2u(__floats2half2_rn(p10, p11));
        }

        // --- O += P @ V (pure MMA burst, fragments preloaded) ---
        #pragma unroll
        for (int kb = 0; kb < 4; ++kb)
            #pragma unroll
            for (int ep = 0; ep < 4; ++ep) {
                mma_f16(oc[2 * ep],     ah_[kb], vfr[kb][ep][0], vfr[kb][ep][1]);
                mma_f16(oc[2 * ep + 1], ah_[kb], vfr[kb][ep][2], vfr[kb][ep][3]);
            }
    }

    // ---- rowsum reduce within the 4-thread column groups -> smem ----
    rs0 += __shfl_xor_sync(0xffffffffu, rs0, 1);
    rs0 += __shfl_xor_sync(0xffffffffu, rs0, 2);
    rs1 += __shfl_xor_sync(0xffffffffu, rs1, 1);
    rs1 += __shfl_xor_sync(0xffffffffu, rs1, 2);
    if (t == 0) {
        rowsum_s[r0] = rs0;
        rowsum_s[r0 + 8] = rs1;
    }

    // ---- out epilogue (normalized, from registers) ----
    {
        float* o0 = out + (bS + gi0) * ND;
        float* o1 = out + (bS + gi1) * ND;
        if (gi0 == 0) {
            const float* vr = v + bS * ND;  // row 0: softmax over single -50000 diag
            #pragma unroll
            for (int nb = 0; nb < 8; ++nb) {
                int c = nb * 8 + 2 * t;
                *(float2*)(o0 + c) = *(const float2*)(vr + c);
            }
        } else {
            float i0 = 1.0f / rs0;
            #pragma unroll
            for (int nb = 0; nb < 8; ++nb) {
                int c = nb * 8 + 2 * t;
                *(float2*)(o0 + c) = make_float2(oc[nb][0] * i0, oc[nb][1] * i0);
            }
        }
        float i1 = 1.0f / rs1;
        #pragma unroll
        for (int nb = 0; nb < 8; ++nb) {
            int c = nb * 8 + 2 * t;
            *(float2*)(o1 + c) = make_float2(oc[nb][2] * i1, oc[nb][3] * i1);
        }
    }

    // ---- in-CTA normalize sweep (lower part) + zero-fill (upper part) ----
    __syncthreads();   // rowsum_s + all attn STGs visible CTA-wide
    {
        int r = tid >> 1;
        float rs = rowsum_s[r];
        float inv = rs > 0.f ? 1.0f / rs : 0.f;
        float* rowp = attn_b + (size_t)(rt * 64 + r) * NS;
        const int cl = nt * 64;
        for (int c = (tid & 1) * 4; c < cl; c += 8) {
            float4 a = *(float4*)(rowp + c);
            a.x *= inv; a.y *= inv; a.z *= inv; a.w *= inv;
            *(float4*)(rowp + c) = a;
        }
        float4 z = make_float4(0.f, 0.f, 0.f, 0.f);
        for (int c = cl + (tid & 1) * 4; c < NS; c += 8)
            *(float4*)(rowp + c) = z;
    }
    if (rt == 0 && tid == 0) attn_b[0] = 1.0f;  // row 0: softmax over single diag entry
}

// ---------------------------------------------------------------------------
extern "C" void kernel_launch(void* const* d_in, const int* in_sizes, int n_in,
                              void* d_out, int out_size) {
    const float* qk = (const float*)d_in[0];
    const float* v  = (const float*)d_in[1];
    float* out  = (float*)d_out;
    float* attn = out + (size_t)NB * NS * ND;

    cudaFuncSetAttribute(attn_main, cudaFuncAttributeMaxDynamicSharedMemorySize, SMEM_SZ);
    prep_kernel<<<NB * NS / 8, 256>>>(qk, v);
    attn_main<<<256, 128, SMEM_SZ>>>(v, out, attn);
}

// round 10
// speedup vs baseline: 1.2954x; 1.2954x over previous
#include <cuda_runtime.h>
#include <cuda_fp16.h>
#include <cstdint>

#define NB 4
#define NS 4096
#define ND 64
#define SCALE 0.125f
#define STR 72u          // fp16 elems per smem row (144 B -> LDSM conflict-free)
#define TBYTES 9216u     // one 64x72 fp16 tile
#define BUFB 27648u      // one buffer group: KH + KL + VH

// dynamic smem: [Q 9216][3 x (KH, KL, VH)]; O-combine buffer reuses O_B region
#define O_Q 0u
#define O_B 9216u
#define SMEM_SZ 92160u

// pre-split fp16 operand arrays (uint32 = fp16x2), rows of 128 B
__device__ __align__(128) uint32_t g_qh[(size_t)NB * NS * 32];  // fp16(q*SCALE)
__device__ __align__(128) uint32_t g_kh[(size_t)NB * NS * 32];  // fp16 hi of kn
__device__ __align__(128) uint32_t g_kl[(size_t)NB * NS * 32];  // fp16 lo of kn
__device__ __align__(128) uint32_t g_vh[(size_t)NB * NS * 32];  // fp16(v)
__device__ float g_shift[NB * NS];

// ------------------------------------------------------------- PTX helpers
__device__ __forceinline__ uint32_t smem_u32(const void* p) {
    uint32_t a;
    asm("{ .reg .u64 t; cvta.to.shared.u64 t, %1; cvt.u32.u64 %0, t; }" : "=r"(a) : "l"(p));
    return a;
}
__device__ __forceinline__ uint64_t gaddr(const void* p) {
    uint64_t a;
    asm("cvta.to.global.u64 %0, %1;" : "=l"(a) : "l"(p));
    return a;
}
__device__ __forceinline__ void cp16(uint32_t dst, uint64_t src) {
    asm volatile("cp.async.cg.shared.global [%0], [%1], 16;" ::"r"(dst), "l"(src));
}
#define CP_COMMIT() asm volatile("cp.async.commit_group;" ::: "memory")
#define CP_WAIT1()  asm volatile("cp.async.wait_group 1;" ::: "memory")

__device__ __forceinline__ void ldsm4(uint32_t* d, uint32_t a) {
    asm volatile("ldmatrix.sync.aligned.m8n8.x4.shared.b16 {%0,%1,%2,%3}, [%4];"
                 : "=r"(d[0]), "=r"(d[1]), "=r"(d[2]), "=r"(d[3]) : "r"(a));
}
__device__ __forceinline__ void ldsm4t(uint32_t* d, uint32_t a) {
    asm volatile("ldmatrix.sync.aligned.m8n8.x4.trans.shared.b16 {%0,%1,%2,%3}, [%4];"
                 : "=r"(d[0]), "=r"(d[1]), "=r"(d[2]), "=r"(d[3]) : "r"(a));
}
__device__ __forceinline__ void mma_f16(float* c, const uint32_t* a, uint32_t b0, uint32_t b1) {
    asm volatile("mma.sync.aligned.m16n8k16.row.col.f32.f16.f16.f32 "
                 "{%0,%1,%2,%3}, {%4,%5,%6,%7}, {%8,%9}, {%0,%1,%2,%3};"
                 : "+f"(c[0]), "+f"(c[1]), "+f"(c[2]), "+f"(c[3])
                 : "r"(a[0]), "r"(a[1]), "r"(a[2]), "r"(a[3]), "r"(b0), "r"(b1));
}
__device__ __forceinline__ uint32_t h2u(__half2 h) { return *reinterpret_cast<uint32_t*>(&h); }
__device__ __forceinline__ void splith(float a, float b, uint32_t& hi, uint32_t& lo) {
    __half2 h = __floats2half2_rn(a, b);
    float2 f = __half22float2(h);
    __half2 l = __floats2half2_rn(a - f.x, b - f.y);
    hi = h2u(h);
    lo = h2u(l);
}

// ---------------------------------------------------------------------------
// Kernel 1: norms -> shift; fp16 Q*SCALE, split Kn (hi/lo), fp16 V.
// ---------------------------------------------------------------------------
__global__ void prep_kernel(const float* __restrict__ qk, const float* __restrict__ v) {
    int row = blockIdx.x * 8 + (threadIdx.x >> 5);
    int lane = threadIdx.x & 31;
    float2 q = *(const float2*)(qk + (size_t)row * ND + lane * 2);
    float ss = q.x * q.x + q.y * q.y;
    #pragma unroll
    for (int o = 16; o >= 1; o >>= 1) ss += __shfl_xor_sync(0xffffffffu, ss, o);
    float nrm = fmaxf(sqrtf(ss), 1e-12f);
    float inv = 1.0f / nrm;
    size_t w = (size_t)row * 32 + lane;
    g_qh[w] = h2u(__floats2half2_rn(q.x * SCALE, q.y * SCALE));
    uint32_t hi, lo;
    splith(q.x * inv, q.y * inv, hi, lo);
    g_kh[w] = hi; g_kl[w] = lo;
    float2 vv = *(const float2*)(v + (size_t)row * ND + lane * 2);
    g_vh[w] = h2u(__floats2half2_rn(vv.x, vv.y));
    if (lane == 0) g_shift[row] = nrm * SCALE;
}

// ---------------------------------------------------------------------------
// Kernel 2: fused attention, 8 warps = 4 row-groups x 2 col-halves.
// Each warp: S[16x32] (2-term) + partial O over its 32 j-cols (1-term).
// Column-half O partials combined via smem; in-CTA normalize sweep.
// Shifts loaded per-thread via LDG (no smem race across column-half warps).
// ---------------------------------------------------------------------------
__global__ __launch_bounds__(256, 2)
void attn_main(const float* __restrict__ v,
               float* __restrict__ out, float* __restrict__ attn)
{
    extern __shared__ char smc[];
    const uint32_t sb = smem_u32(smc);
    const int tid = threadIdx.x, lane = tid & 31, w = tid >> 5;
    const int wy = w & 3, wx = w >> 2;   // row group (16 rows), col half (32 j-cols)

    // balanced schedule: paired SMs sum to 65 tile-iters
    int l = blockIdx.x, rt, b;
    if (l < 40)       { rt = 63 - (l >> 2); b = l & 3; }
    else if (l < 148) { int i = l - 40; rt = 53 - (i >> 2); b = i & 3; }
    else              { int i = l - 148; rt = i >> 2; b = i & 3; }
    const size_t bS = (size_t)b * NS;
    const int nt = rt + 1;

    __shared__ float rspart[2][64];

    const uint64_t gqh = gaddr(g_qh);
    const uint64_t gkh = gaddr(g_kh), gkl = gaddr(g_kl);
    const uint64_t gvh = gaddr(g_vh);

    auto issue_kv = [&](int ct, uint32_t buf) {
        size_t t0 = (bS + (size_t)ct * 64) * 128;
        uint32_t kb = sb + O_B + buf * BUFB;
        #pragma unroll
        for (int c = 0; c < 2; ++c) {
            int idx = tid * 2 + c, r = idx >> 3, c8 = idx & 7;
            uint32_t so = (uint32_t)(r * 144 + c8 * 16);
            uint64_t go = t0 + (size_t)r * 128 + c8 * 16;
            cp16(kb + so, gkh + go);
            cp16(kb + TBYTES + so, gkl + go);
            cp16(kb + 2 * TBYTES + so, gvh + go);
        }
    };
    // prologue: G0 = Q + tile0; G1 = tile1 (or empty)
    {
        size_t q0 = (bS + (size_t)rt * 64) * 128;
        #pragma unroll
        for (int c = 0; c < 2; ++c) {
            int idx = tid * 2 + c, r = idx >> 3, c8 = idx & 7;
            cp16(sb + O_Q + (uint32_t)(r * 144 + c8 * 16),
                 gqh + q0 + (size_t)r * 128 + c8 * 16);
        }
        issue_kv(0, 0);
        CP_COMMIT();
        if (nt > 1) issue_kv(1, 1);
        CP_COMMIT();
    }

    // ldmatrix byte-offset helpers (within a tile)
    const uint32_t A_off  = (uint32_t)(((lane & 15) * STR + ((lane >> 4) << 3)) * 2);
    const uint32_t B_off  = (uint32_t)(((((lane >> 4) << 3) + (lane & 7)) * STR + (((lane >> 3) & 1) << 3)) * 2);

    const int g = lane >> 2, t = lane & 3;
    const int r0 = wy * 16 + g;
    const int gi0 = rt * 64 + r0, gi1 = gi0 + 8;
    const float sh0 = g_shift[bS + gi0];   // LDG: race-free, consistent per row
    const float sh1 = g_shift[bS + gi1];
    float* attn_b = attn + (size_t)b * NS * NS;
    float* arow0 = attn_b + (size_t)gi0 * NS;
    float* arow1 = attn_b + (size_t)gi1 * NS;

    float oc[8][4] = {};       // partial O[16 x 64] over this warp's j-half
    float rs0 = 0.f, rs1 = 0.f;

    for (int ct = 0; ct < nt; ++ct) {
        const uint32_t buf = (uint32_t)(ct % 3);
        CP_WAIT1();            // tile ct ready (newest group may be in flight)
        __syncthreads();
        if (ct + 2 < nt) issue_kv(ct + 2, (uint32_t)((ct + 2) % 3));
        CP_COMMIT();

        // --- preload this warp's V fragments: rows wx*32.., all 64 e-cols ---
        uint32_t vfr[2][4][4];
        const uint32_t vhb = sb + O_B + buf * BUFB + 2 * TBYTES
                           + (uint32_t)(wx * 32 * STR * 2);
        #pragma unroll
        for (int kb = 0; kb < 2; ++kb)
            #pragma unroll
            for (int ep = 0; ep < 4; ++ep)
                ldsm4t(vfr[kb][ep], vhb + A_off + (uint32_t)(kb * 16 * STR * 2) + (uint32_t)(ep * 32));

        // --- S[16x32] = Qs @ Kn^T (2-term) over this warp's j-half ---
        float sc[4][4] = {};
        const uint32_t khb = sb + O_B + buf * BUFB + (uint32_t)(wx * 32 * STR * 2);
        const uint32_t klb = khb + TBYTES;
        #pragma unroll
        for (int k = 0; k < 4; ++k) {
            uint32_t aq[4], bh[4], bl[4];
            uint32_t kcol = (uint32_t)(k * 32);
            ldsm4(aq, sb + O_Q + A_off + kcol + (uint32_t)(wy * 16 * STR * 2));
            #pragma unroll
            for (int np = 0; np < 2; ++np) {
                uint32_t jo = (uint32_t)(np * 16 * STR * 2);
                ldsm4(bh, khb + B_off + jo + kcol);
                ldsm4(bl, klb + B_off + jo + kcol);
                mma_f16(sc[2 * np],     aq, bh[0], bh[1]);
                mma_f16(sc[2 * np],     aq, bl[0], bl[1]);
                mma_f16(sc[2 * np + 1], aq, bh[2], bh[3]);
                mma_f16(sc[2 * np + 1], aq, bl[2], bl[3]);
            }
        }

        // --- exp + mask + unnormalized attn store + fp16 A-frag repack ---
        uint32_t ah_[2][4];
        const int gjb = ct * 64 + wx * 32 + 2 * t;
        #pragma unroll
        for (int nb = 0; nb < 4; ++nb) {
            int gj = gjb + nb * 8;
            float p00 = (gj < gi0)     ? __expf(sc[nb][0] - sh0) : 0.f;
            float p01 = (gj + 1 < gi0) ? __expf(sc[nb][1] - sh0) : 0.f;
            float p10 = (gj < gi1)     ? __expf(sc[nb][2] - sh1) : 0.f;
            float p11 = (gj + 1 < gi1) ? __expf(sc[nb][3] - sh1) : 0.f;
            rs0 += p00 + p01;
            rs1 += p10 + p11;
            *(float2*)(arow0 + gj) = make_float2(p00, p01);
            *(float2*)(arow1 + gj) = make_float2(p10, p11);
            int kb = nb >> 1, o = (nb & 1) * 2;
            ah_[kb][o]     = h2u(__floats2half2_rn(p00, p01));
            ah_[kb][o + 1] = h2u(__floats2half2_rn(p10, p11));
        }

        // --- O_partial += P @ V (pure MMA burst, 16 MMAs) ---
        #pragma unroll
        for (int kb = 0; kb < 2; ++kb)
            #pragma unroll
            for (int ep = 0; ep < 4; ++ep) {
                mma_f16(oc[2 * ep],     ah_[kb], vfr[kb][ep][0], vfr[kb][ep][1]);
                mma_f16(oc[2 * ep + 1], ah_[kb], vfr[kb][ep][2], vfr[kb][ep][3]);
            }
    }

    // ---- rowsum partial (this warp's 32 cols) -> smem ----
    rs0 += __shfl_xor_sync(0xffffffffu, rs0, 1);
    rs0 += __shfl_xor_sync(0xffffffffu, rs0, 2);
    rs1 += __shfl_xor_sync(0xffffffffu, rs1, 1);
    rs1 += __shfl_xor_sync(0xffffffffu, rs1, 2);
    if (t == 0) {
        rspart[wx][r0] = rs0;
        rspart[wx][r0 + 8] = rs1;
    }
    __syncthreads();   // rspart visible; all loop-buffer LDSMs done

    // ---- combine column-half O partials via padded smem buffer ----
    float* obuf = (float*)(smc + O_B);   // 64 x 66 floats (reuse KV region)
    if (wx == 1) {
        #pragma unroll
        for (int nb = 0; nb < 8; ++nb) {
            int c = nb * 8 + 2 * t;
            obuf[r0 * 66 + c]       = oc[nb][0];
            obuf[r0 * 66 + c + 1]   = oc[nb][1];
            obuf[(r0 + 8) * 66 + c]     = oc[nb][2];
            obuf[(r0 + 8) * 66 + c + 1] = oc[nb][3];
        }
    }
    __syncthreads();
    if (wx == 0) {
        float rt0 = rspart[0][r0] + rspart[1][r0];
        float rt1 = rspart[0][r0 + 8] + rspart[1][r0 + 8];
        float* o0 = out + (bS + gi0) * ND;
        float* o1 = out + (bS + gi1) * ND;
        if (gi0 == 0) {
            const float* vr = v + bS * ND;  // row 0: softmax over single -50000 diag
            #pragma unroll
            for (int nb = 0; nb < 8; ++nb) {
                int c = nb * 8 + 2 * t;
                *(float2*)(o0 + c) = *(const float2*)(vr + c);
            }
        } else {
            float i0 = 1.0f / rt0;
            #pragma unroll
            for (int nb = 0; nb < 8; ++nb) {
                int c = nb * 8 + 2 * t;
                *(float2*)(o0 + c) = make_float2((oc[nb][0] + obuf[r0 * 66 + c]) * i0,
                                                 (oc[nb][1] + obuf[r0 * 66 + c + 1]) * i0);
            }
        }
        float i1 = 1.0f / rt1;
        #pragma unroll
        for (int nb = 0; nb < 8; ++nb) {
            int c = nb * 8 + 2 * t;
            *(float2*)(o1 + c) = make_float2((oc[nb][2] + obuf[(r0 + 8) * 66 + c]) * i1,
                                             (oc[nb][3] + obuf[(r0 + 8) * 66 + c + 1]) * i1);
        }
    }

    // ---- in-CTA normalize sweep (lower) + zero-fill (upper), 4 thr/row ----
    {
        int r = tid >> 2;
        float rs = rspart[0][r] + rspart[1][r];
        float inv = rs > 0.f ? 1.0f / rs : 0.f;
        float* rowp = attn_b + (size_t)(rt * 64 + r) * NS;
        const int cl = nt * 64;
        for (int c = (tid & 3) * 4; c < cl; c += 16) {
            float4 a = *(float4*)(rowp + c);
            a.x *= inv; a.y *= inv; a.z *= inv; a.w *= inv;
            *(float4*)(rowp + c) = a;
        }
        float4 z = make_float4(0.f, 0.f, 0.f, 0.f);
        for (int c = cl + (tid & 3) * 4; c < NS; c += 16)
            *(float4*)(rowp + c) = z;
    }
    if (rt == 0 && tid == 0) attn_b[0] = 1.0f;  // row 0: softmax over single diag entry
}

// ---------------------------------------------------------------------------
extern "C" void kernel_launch(void* const* d_in, const int* in_sizes, int n_in,
                              void* d_out, int out_size) {
    const float* qk = (const float*)d_in[0];
    const float* v  = (const float*)d_in[1];
    float* out  = (float*)d_out;
    float* attn = out + (size_t)NB * NS * ND;

    cudaFuncSetAttribute(attn_main, cudaFuncAttributeMaxDynamicSharedMemorySize, SMEM_SZ);
    prep_kernel<<<NB * NS / 8, 256>>>(qk, v);
    attn_main<<<256, 256, SMEM_SZ>>>(v, out, attn);
}